// round 4
// baseline (speedup 1.0000x reference)
#include <cuda_runtime.h>
#include <cstdint>

#define N_NODES 2000
#define E_EDGES 64000
#define ED_DIM  16
#define ENH_DIM 128
#define H_DIM   64
#define HH      4096   // H*H
#define T_STEPS 8

// ---------------- scratch (device globals; no allocation) ----------------
__device__ float g_h1 [(size_t)E_EDGES * ENH_DIM];           // 32.8 MB
__device__ float g_A  [(size_t)E_EDGES * HH];                // 1.05 GB, layout A[e][j*64+i]
__device__ float g_W2p[(size_t)HH * ENH_DIM];                // W2 permuted+transposed: [c'][k]
__device__ float g_b2p[HH];
__device__ float g_m  [N_NODES * H_DIM];
__device__ float g_x0 [N_NODES * H_DIM];
__device__ float g_x1 [N_NODES * H_DIM];

// ---------------- f32x2 helpers ----------------
__device__ __forceinline__ unsigned long long ffma2(unsigned long long a,
                                                    unsigned long long b,
                                                    unsigned long long c) {
    unsigned long long d;
    asm("fma.rn.f32x2 %0, %1, %2, %3;" : "=l"(d) : "l"(a), "l"(b), "l"(c));
    return d;
}
__device__ __forceinline__ unsigned long long splat2(float x) {
    unsigned long long d;
    asm("mov.b64 %0, {%1, %1};" : "=l"(d) : "f"(x));
    return d;
}

// ---------------- h1 = relu(ef @ W1 + b1) ----------------
__global__ __launch_bounds__(128) void k_h1(const float* __restrict__ edge_data,
                                            const int*   __restrict__ edges,
                                            const float* __restrict__ W1,
                                            const float* __restrict__ b1) {
    int e = blockIdx.x;
    __shared__ float ef[ED_DIM];
    int src = edges[2 * e], tgt = edges[2 * e + 1];
    if (threadIdx.x < ED_DIM)
        ef[threadIdx.x] = edge_data[((size_t)src * N_NODES + tgt) * ED_DIM + threadIdx.x];
    __syncthreads();
    int u = threadIdx.x;
    float acc = b1[u];
#pragma unroll
    for (int k = 0; k < ED_DIM; k++) acc += ef[k] * W1[k * ENH_DIM + u];
    g_h1[(size_t)e * ENH_DIM + u] = fmaxf(acc, 0.f);
}

// ---------------- permute W2 -> [c'][k] with c' = j*64+i (orig col = i*64+j) ----------------
__global__ void k_permW2(const float* __restrict__ W2, const float* __restrict__ b2) {
    int idx = blockIdx.x * blockDim.x + threadIdx.x;
    if (idx < ENH_DIM * HH) {
        int cp = idx >> 7, k = idx & 127;                // out layout [cp][k]
        int orig = ((cp & 63) << 6) + (cp >> 6);         // i*64 + j
        g_W2p[idx] = W2[(size_t)k * HH + orig];
    }
    if (idx < HH) g_b2p[idx] = b2[((idx & 63) << 6) + (idx >> 6)];
}

// ---------------- A' = relu(h1 @ W2p + b2p), stored g_A[e][c'] ----------------
// BM=128 (edges), BN=64 (cols), K=128 entire. 256 threads, 8x4 microtile,
// k-paired f32x2 accumulators (both operands are natural 64-bit k-pairs).
#define AS_STRIDE 132
#define GEMM_SMEM_BYTES ((128 * AS_STRIDE + 64 * AS_STRIDE) * 4)

__global__ __launch_bounds__(256, 1) void k_gemmA() {
    extern __shared__ float sh[];
    float* As = sh;                    // [128][132]  (row-major in k)
    float* Bs = sh + 128 * AS_STRIDE;  // [64][132]   (col-major: [c][k])
    const int t = threadIdx.x;
    const int eBase = blockIdx.x * 128;
    const int cBase = blockIdx.y * 64;

    for (int i = t * 4; i < 128 * 128; i += 1024) {
        int r = i >> 7, k = i & 127;
        *reinterpret_cast<float4*>(&As[r * AS_STRIDE + k]) =
            *reinterpret_cast<const float4*>(&g_h1[(size_t)(eBase + r) * ENH_DIM + k]);
    }
    for (int i = t * 4; i < 64 * 128; i += 1024) {
        int c = i >> 7, k = i & 127;
        *reinterpret_cast<float4*>(&Bs[c * AS_STRIDE + k]) =
            *reinterpret_cast<const float4*>(&g_W2p[(size_t)(cBase + c) * ENH_DIM + k]);
    }
    __syncthreads();

    const int ty = t >> 4;  // 0..15, rows ty + 16*rr
    const int tx = t & 15;  // 0..15, cols tx + 16*cc
    unsigned long long acc[8][4];
#pragma unroll
    for (int rr = 0; rr < 8; rr++)
#pragma unroll
        for (int cc = 0; cc < 4; cc++) acc[rr][cc] = 0ull;

#pragma unroll 4
    for (int k = 0; k < 128; k += 2) {
        unsigned long long a[8], b[4];
#pragma unroll
        for (int rr = 0; rr < 8; rr++)
            a[rr] = *reinterpret_cast<const unsigned long long*>(&As[(ty + 16 * rr) * AS_STRIDE + k]);
#pragma unroll
        for (int cc = 0; cc < 4; cc++)
            b[cc] = *reinterpret_cast<const unsigned long long*>(&Bs[(tx + 16 * cc) * AS_STRIDE + k]);
#pragma unroll
        for (int rr = 0; rr < 8; rr++)
#pragma unroll
            for (int cc = 0; cc < 4; cc++)
                acc[rr][cc] = ffma2(a[rr], b[cc], acc[rr][cc]);
    }

    float bb[4];
#pragma unroll
    for (int cc = 0; cc < 4; cc++) bb[cc] = g_b2p[cBase + tx + 16 * cc];

#pragma unroll
    for (int rr = 0; rr < 8; rr++) {
        size_t rowb = (size_t)(eBase + ty + 16 * rr) * HH + cBase;
#pragma unroll
        for (int cc = 0; cc < 4; cc++) {
            float2 p = *reinterpret_cast<float2*>(&acc[rr][cc]);
            g_A[rowb + tx + 16 * cc] = fmaxf(p.x + p.y + bb[cc], 0.f);
        }
    }
}

// ---------------- msg + scatter: warp per edge ----------------
// A stored as [e][j*64 + i]: lane l accumulates msg rows 2l, 2l+1 via
// coalesced LDG.64 of row j; x[src][j] broadcast by shfl. Then atomicAdd.
__global__ __launch_bounds__(256) void k_msg(const float* __restrict__ x,
                                             const int*   __restrict__ edges) {
    int wid = (blockIdx.x * blockDim.x + threadIdx.x) >> 5;
    if (wid >= E_EDGES) return;
    int lane = threadIdx.x & 31;
    int src = edges[2 * wid], tgt = edges[2 * wid + 1];
    float xlo = x[src * H_DIM + lane];
    float xhi = x[src * H_DIM + 32 + lane];
    const float* Ap = g_A + (size_t)wid * HH + 2 * lane;

    unsigned long long acc = 0ull;
#pragma unroll
    for (int j = 0; j < H_DIM; j++) {
        float xj = (j < 32) ? __shfl_sync(0xffffffffu, xlo, j)
                            : __shfl_sync(0xffffffffu, xhi, j - 32);
        unsigned long long av = *reinterpret_cast<const unsigned long long*>(Ap + j * H_DIM);
        acc = ffma2(av, splat2(xj), acc);
    }
    float2 mv = *reinterpret_cast<float2*>(&acc);
    int r0 = 2 * lane;
    atomicAdd(&g_m[tgt * H_DIM + r0],     mv.x);
    atomicAdd(&g_m[tgt * H_DIM + r0 + 1], mv.y);
    if (src != tgt) {
        atomicAdd(&g_m[src * H_DIM + r0],     mv.x);
        atomicAdd(&g_m[src * H_DIM + r0 + 1], mv.y);
    }
}

// ---------------- GRU cell: 16 nodes/block, 4 nodes/thread ----------------
#define NPB 16
__global__ __launch_bounds__(256) void k_gru(const float* __restrict__ xin,
                                             float*       __restrict__ xout,
                                             const float* __restrict__ Wih,
                                             const float* __restrict__ Whh,
                                             const float* __restrict__ bih,
                                             const float* __restrict__ bhh) {
    __shared__ float sx[NPB * H_DIM];
    __shared__ float sm[NPB * H_DIM];
    int t = threadIdx.x;
    int base = blockIdx.x * NPB * H_DIM;
    for (int i = t; i < NPB * H_DIM; i += 256) {
        sx[i] = xin[base + i];
        sm[i] = g_m[base + i];
        g_m[base + i] = 0.f;   // reset accumulator for next step / next replay
    }
    __syncthreads();

    int c  = t & 63;
    int ng = t >> 6;  // handles nodes ng*4 .. ng*4+3
    float aR[4], aZ[4], aN[4], hR[4], hZ[4], hN[4];
    float biR = bih[c], biZ = bih[64 + c], biN = bih[128 + c];
    float bhR = bhh[c], bhZ = bhh[64 + c], bhN = bhh[128 + c];
#pragma unroll
    for (int q = 0; q < 4; q++) {
        aR[q] = biR; aZ[q] = biZ; aN[q] = biN;
        hR[q] = bhR; hZ[q] = bhZ; hN[q] = bhN;
    }
#pragma unroll 4
    for (int k = 0; k < H_DIM; k++) {
        float w0 = Wih[k * 192 + c], w1 = Wih[k * 192 + 64 + c], w2 = Wih[k * 192 + 128 + c];
        float v0 = Wih[(64 + k) * 192 + c], v1 = Wih[(64 + k) * 192 + 64 + c], v2 = Wih[(64 + k) * 192 + 128 + c];
        float u0 = Whh[k * 192 + c], u1 = Whh[k * 192 + 64 + c], u2 = Whh[k * 192 + 128 + c];
#pragma unroll
        for (int q = 0; q < 4; q++) {
            float xv = sx[(ng * 4 + q) * H_DIM + k];
            float mv = sm[(ng * 4 + q) * H_DIM + k];
            aR[q] += xv * w0 + mv * v0;
            aZ[q] += xv * w1 + mv * v1;
            aN[q] += xv * w2 + mv * v2;
            hR[q] += xv * u0;
            hZ[q] += xv * u1;
            hN[q] += xv * u2;
        }
    }
#pragma unroll
    for (int q = 0; q < 4; q++) {
        float r = 1.f / (1.f + expf(-(aR[q] + hR[q])));
        float z = 1.f / (1.f + expf(-(aZ[q] + hZ[q])));
        float n = tanhf(aN[q] + r * hN[q]);
        float h = sx[(ng * 4 + q) * H_DIM + c];
        xout[base + (ng * 4 + q) * H_DIM + c] = (1.f - z) * n + z * h;
    }
}

// ---------------- launch ----------------
extern "C" void kernel_launch(void* const* d_in, const int* in_sizes, int n_in,
                              void* d_out, int out_size) {
    const float* x         = (const float*)d_in[0];
    const float* edge_data = (const float*)d_in[2];
    const int*   edges     = (const int*)  d_in[3];
    const float* W1        = (const float*)d_in[5];
    const float* b1        = (const float*)d_in[6];
    const float* W2        = (const float*)d_in[7];
    const float* b2        = (const float*)d_in[8];
    const float* W_ih      = (const float*)d_in[9];
    const float* W_hh      = (const float*)d_in[10];
    const float* b_ih      = (const float*)d_in[11];
    const float* b_hh      = (const float*)d_in[12];
    float* out = (float*)d_out;

    float *px0 = nullptr, *px1 = nullptr, *pm = nullptr;
    cudaGetSymbolAddress((void**)&px0, g_x0);
    cudaGetSymbolAddress((void**)&px1, g_x1);
    cudaGetSymbolAddress((void**)&pm,  g_m);

    cudaMemcpyAsync(px0, x, (size_t)N_NODES * H_DIM * sizeof(float),
                    cudaMemcpyDeviceToDevice, 0);
    cudaMemsetAsync(pm, 0, (size_t)N_NODES * H_DIM * sizeof(float), 0);

    k_h1<<<E_EDGES, 128>>>(edge_data, edges, W1, b1);
    k_permW2<<<(ENH_DIM * HH + 255) / 256, 256>>>(W2, b2);

    cudaFuncSetAttribute(k_gemmA, cudaFuncAttributeMaxDynamicSharedMemorySize,
                         GEMM_SMEM_BYTES);
    k_gemmA<<<dim3(E_EDGES / 128, HH / 64), 256, GEMM_SMEM_BYTES>>>();

    for (int t = 0; t < T_STEPS; t++) {
        const float* xin = (t & 1) ? px1 : px0;
        float* xout = (t == T_STEPS - 1) ? out : ((t & 1) ? px0 : px1);
        k_msg<<<(E_EDGES * 32) / 256, 256>>>(xin, edges);
        k_gru<<<N_NODES / NPB, 256>>>(xin, xout, W_ih, W_hh, b_ih, b_hh);
    }
}

// round 6
// speedup vs baseline: 1.1715x; 1.1715x over previous
#include <cuda_runtime.h>
#include <cstdint>

#define N_NODES 2000
#define E_EDGES 64000
#define ED_DIM  16
#define ENH_DIM 128
#define H_DIM   64
#define HH      4096   // H*H
#define T_STEPS 8

// ---------------- scratch (device globals; no allocation) ----------------
__device__ float          g_h1 [(size_t)E_EDGES * ENH_DIM];   // 32.8 MB
__device__ unsigned short g_Aq [(size_t)E_EDGES * HH];        // 524 MB, A[e][j*64+i] uint16 fixed-point
__device__ float          g_s  [(size_t)E_EDGES * H_DIM];     // 16.4 MB, per-(edge,j) scale (row max)
__device__ float          g_W2p[(size_t)HH * ENH_DIM];        // W2 permuted+transposed: [c'][k]
__device__ float          g_b2p[HH];
__device__ float          g_m  [N_NODES * H_DIM];
__device__ float          g_x0 [N_NODES * H_DIM];
__device__ float          g_x1 [N_NODES * H_DIM];

// ---------------- f32x2 helpers ----------------
__device__ __forceinline__ unsigned long long ffma2(unsigned long long a,
                                                    unsigned long long b,
                                                    unsigned long long c) {
    unsigned long long d;
    asm("fma.rn.f32x2 %0, %1, %2, %3;" : "=l"(d) : "l"(a), "l"(b), "l"(c));
    return d;
}
__device__ __forceinline__ unsigned long long splat2(float x) {
    unsigned long long d;
    asm("mov.b64 %0, {%1, %1};" : "=l"(d) : "f"(x));
    return d;
}
__device__ __forceinline__ unsigned long long pack2(float lo, float hi) {
    unsigned long long d;
    asm("mov.b64 %0, {%1, %2};" : "=l"(d) : "f"(lo), "f"(hi));
    return d;
}

// ---------------- h1 = relu(ef @ W1 + b1) ----------------
__global__ __launch_bounds__(128) void k_h1(const float* __restrict__ edge_data,
                                            const int*   __restrict__ edges,
                                            const float* __restrict__ W1,
                                            const float* __restrict__ b1) {
    int e = blockIdx.x;
    __shared__ float ef[ED_DIM];
    int src = edges[2 * e], tgt = edges[2 * e + 1];
    if (threadIdx.x < ED_DIM)
        ef[threadIdx.x] = edge_data[((size_t)src * N_NODES + tgt) * ED_DIM + threadIdx.x];
    __syncthreads();
    int u = threadIdx.x;
    float acc = b1[u];
#pragma unroll
    for (int k = 0; k < ED_DIM; k++) acc += ef[k] * W1[k * ENH_DIM + u];
    g_h1[(size_t)e * ENH_DIM + u] = fmaxf(acc, 0.f);
}

// ---------------- permute W2 -> [c'][k] with c' = j*64+i (orig col = i*64+j) ----------------
__global__ void k_permW2(const float* __restrict__ W2, const float* __restrict__ b2) {
    int idx = blockIdx.x * blockDim.x + threadIdx.x;
    if (idx < ENH_DIM * HH) {
        int cp = idx >> 7, k = idx & 127;                // out layout [cp][k]
        int orig = ((cp & 63) << 6) + (cp >> 6);         // i*64 + j
        g_W2p[idx] = W2[(size_t)k * HH + orig];
    }
    if (idx < HH) g_b2p[idx] = b2[((idx & 63) << 6) + (idx >> 6)];
}

// ---------------- A' = relu(h1 @ W2p + b2p) -> uint16 + exact per-(e,j) scale ----------------
// BM=128 (edges), BN=64 (cols = all i for one j), K=128. 256 threads, 8x4
// microtile, k-paired f32x2 accumulators. Epilogue: 16-lane shfl max over i
// gives exact s[e][j]; quantize q = rne(v * 65535 / s).
// Grid: x = j (64), y = edge-blocks (500) so a wave shares h1 rows in L2.
#define AS_STRIDE 132
#define GEMM_SMEM_BYTES ((128 * AS_STRIDE + 64 * AS_STRIDE) * 4)

__global__ __launch_bounds__(256, 1) void k_gemmA() {
    extern __shared__ float sh[];
    float* As = sh;                    // [128][132]  (row-major in k)
    float* Bs = sh + 128 * AS_STRIDE;  // [64][132]   (col-major: [c][k])
    const int t = threadIdx.x;
    const int eBase = blockIdx.y * 128;
    const int cBase = blockIdx.x * 64;

    for (int i = t * 4; i < 128 * 128; i += 1024) {
        int r = i >> 7, k = i & 127;
        *reinterpret_cast<float4*>(&As[r * AS_STRIDE + k]) =
            *reinterpret_cast<const float4*>(&g_h1[(size_t)(eBase + r) * ENH_DIM + k]);
    }
    for (int i = t * 4; i < 64 * 128; i += 1024) {
        int c = i >> 7, k = i & 127;
        *reinterpret_cast<float4*>(&Bs[c * AS_STRIDE + k]) =
            *reinterpret_cast<const float4*>(&g_W2p[(size_t)(cBase + c) * ENH_DIM + k]);
    }
    __syncthreads();

    const int ty = t >> 4;  // 0..15, rows ty + 16*rr
    const int tx = t & 15;  // 0..15, cols tx + 16*cc
    unsigned long long acc[8][4];
#pragma unroll
    for (int rr = 0; rr < 8; rr++)
#pragma unroll
        for (int cc = 0; cc < 4; cc++) acc[rr][cc] = 0ull;

#pragma unroll 4
    for (int k = 0; k < 128; k += 2) {
        unsigned long long a[8], b[4];
#pragma unroll
        for (int rr = 0; rr < 8; rr++)
            a[rr] = *reinterpret_cast<const unsigned long long*>(&As[(ty + 16 * rr) * AS_STRIDE + k]);
#pragma unroll
        for (int cc = 0; cc < 4; cc++)
            b[cc] = *reinterpret_cast<const unsigned long long*>(&Bs[(tx + 16 * cc) * AS_STRIDE + k]);
#pragma unroll
        for (int rr = 0; rr < 8; rr++)
#pragma unroll
            for (int cc = 0; cc < 4; cc++)
                acc[rr][cc] = ffma2(a[rr], b[cc], acc[rr][cc]);
    }

    float bb[4];
#pragma unroll
    for (int cc = 0; cc < 4; cc++) bb[cc] = g_b2p[cBase + tx + 16 * cc];

#pragma unroll
    for (int rr = 0; rr < 8; rr++) {
        float v[4];
#pragma unroll
        for (int cc = 0; cc < 4; cc++) {
            float2 p = *reinterpret_cast<float2*>(&acc[rr][cc]);
            v[cc] = fmaxf(p.x + p.y + bb[cc], 0.f);
        }
        // exact max over the 64 i-columns of this (edge, j) row:
        float mx = fmaxf(fmaxf(v[0], v[1]), fmaxf(v[2], v[3]));
#pragma unroll
        for (int off = 1; off < 16; off <<= 1)
            mx = fmaxf(mx, __shfl_xor_sync(0xffffffffu, mx, off));
        if (tx == 0)
            g_s[(size_t)(eBase + ty + 16 * rr) * H_DIM + blockIdx.x] = mx;
        float rcp = 65535.f / fmaxf(mx, 1e-30f);
        size_t rowb = (size_t)(eBase + ty + 16 * rr) * HH + cBase;
#pragma unroll
        for (int cc = 0; cc < 4; cc++)
            g_Aq[rowb + tx + 16 * cc] = (unsigned short)__float2uint_rn(v[cc] * rcp);
    }
}

// ---------------- msg + scatter: warp per edge ----------------
// A stored uint16 as [e][j*64 + i] with scale s[e][j]: lane l accumulates msg
// rows 2l, 2l+1 via coalesced 32-bit ushort2 loads of row j; scaled x[src][j]
// (x_j * s_ej / 65535) broadcast by shfl. fp32 f32x2 accumulate, then atomicAdd.
__global__ __launch_bounds__(256) void k_msg(const float* __restrict__ x,
                                             const int*   __restrict__ edges) {
    int wid = (blockIdx.x * blockDim.x + threadIdx.x) >> 5;
    if (wid >= E_EDGES) return;
    int lane = threadIdx.x & 31;
    int src = edges[2 * wid], tgt = edges[2 * wid + 1];
    const float inv = 1.f / 65535.f;
    float s0 = g_s[(size_t)wid * H_DIM + lane];
    float s1 = g_s[(size_t)wid * H_DIM + 32 + lane];
    float xlo = x[src * H_DIM + lane]      * s0 * inv;
    float xhi = x[src * H_DIM + 32 + lane] * s1 * inv;
    const ushort2* __restrict__ Ap =
        reinterpret_cast<const ushort2*>(g_Aq + (size_t)wid * HH) + lane;

    unsigned long long acc = 0ull;
#pragma unroll
    for (int j = 0; j < H_DIM; j++) {
        float xj = (j < 32) ? __shfl_sync(0xffffffffu, xlo, j)
                            : __shfl_sync(0xffffffffu, xhi, j - 32);
        ushort2 q = Ap[j * 32];
        acc = ffma2(pack2((float)q.x, (float)q.y), splat2(xj), acc);
    }
    float2 mv = *reinterpret_cast<float2*>(&acc);
    int r0 = 2 * lane;
    atomicAdd(&g_m[tgt * H_DIM + r0],     mv.x);
    atomicAdd(&g_m[tgt * H_DIM + r0 + 1], mv.y);
    if (src != tgt) {
        atomicAdd(&g_m[src * H_DIM + r0],     mv.x);
        atomicAdd(&g_m[src * H_DIM + r0 + 1], mv.y);
    }
}

// ---------------- GRU cell: 16 nodes/block, 4 nodes/thread ----------------
#define NPB 16
__global__ __launch_bounds__(256) void k_gru(const float* __restrict__ xin,
                                             float*       __restrict__ xout,
                                             const float* __restrict__ Wih,
                                             const float* __restrict__ Whh,
                                             const float* __restrict__ bih,
                                             const float* __restrict__ bhh) {
    __shared__ float sx[NPB * H_DIM];
    __shared__ float sm[NPB * H_DIM];
    int t = threadIdx.x;
    int base = blockIdx.x * NPB * H_DIM;
    for (int i = t; i < NPB * H_DIM; i += 256) {
        sx[i] = xin[base + i];
        sm[i] = g_m[base + i];
        g_m[base + i] = 0.f;   // reset accumulator for next step / next replay
    }
    __syncthreads();

    int c  = t & 63;
    int ng = t >> 6;  // handles nodes ng*4 .. ng*4+3
    float aR[4], aZ[4], aN[4], hR[4], hZ[4], hN[4];
    float biR = bih[c], biZ = bih[64 + c], biN = bih[128 + c];
    float bhR = bhh[c], bhZ = bhh[64 + c], bhN = bhh[128 + c];
#pragma unroll
    for (int q = 0; q < 4; q++) {
        aR[q] = biR; aZ[q] = biZ; aN[q] = biN;
        hR[q] = bhR; hZ[q] = bhZ; hN[q] = bhN;
    }
#pragma unroll 4
    for (int k = 0; k < H_DIM; k++) {
        float w0 = Wih[k * 192 + c], w1 = Wih[k * 192 + 64 + c], w2 = Wih[k * 192 + 128 + c];
        float v0 = Wih[(64 + k) * 192 + c], v1 = Wih[(64 + k) * 192 + 64 + c], v2 = Wih[(64 + k) * 192 + 128 + c];
        float u0 = Whh[k * 192 + c], u1 = Whh[k * 192 + 64 + c], u2 = Whh[k * 192 + 128 + c];
#pragma unroll
        for (int q = 0; q < 4; q++) {
            float xv = sx[(ng * 4 + q) * H_DIM + k];
            float mv = sm[(ng * 4 + q) * H_DIM + k];
            aR[q] += xv * w0 + mv * v0;
            aZ[q] += xv * w1 + mv * v1;
            aN[q] += xv * w2 + mv * v2;
            hR[q] += xv * u0;
            hZ[q] += xv * u1;
            hN[q] += xv * u2;
        }
    }
#pragma unroll
    for (int q = 0; q < 4; q++) {
        float r = 1.f / (1.f + expf(-(aR[q] + hR[q])));
        float z = 1.f / (1.f + expf(-(aZ[q] + hZ[q])));
        float n = tanhf(aN[q] + r * hN[q]);
        float h = sx[(ng * 4 + q) * H_DIM + c];
        xout[base + (ng * 4 + q) * H_DIM + c] = (1.f - z) * n + z * h;
    }
}

// ---------------- launch ----------------
extern "C" void kernel_launch(void* const* d_in, const int* in_sizes, int n_in,
                              void* d_out, int out_size) {
    const float* x         = (const float*)d_in[0];
    const float* edge_data = (const float*)d_in[2];
    const int*   edges     = (const int*)  d_in[3];
    const float* W1        = (const float*)d_in[5];
    const float* b1        = (const float*)d_in[6];
    const float* W2        = (const float*)d_in[7];
    const float* b2        = (const float*)d_in[8];
    const float* W_ih      = (const float*)d_in[9];
    const float* W_hh      = (const float*)d_in[10];
    const float* b_ih      = (const float*)d_in[11];
    const float* b_hh      = (const float*)d_in[12];
    float* out = (float*)d_out;

    float *px0 = nullptr, *px1 = nullptr, *pm = nullptr;
    cudaGetSymbolAddress((void**)&px0, g_x0);
    cudaGetSymbolAddress((void**)&px1, g_x1);
    cudaGetSymbolAddress((void**)&pm,  g_m);

    cudaMemcpyAsync(px0, x, (size_t)N_NODES * H_DIM * sizeof(float),
                    cudaMemcpyDeviceToDevice, 0);
    cudaMemsetAsync(pm, 0, (size_t)N_NODES * H_DIM * sizeof(float), 0);

    k_h1<<<E_EDGES, 128>>>(edge_data, edges, W1, b1);
    k_permW2<<<(ENH_DIM * HH + 255) / 256, 256>>>(W2, b2);

    cudaFuncSetAttribute(k_gemmA, cudaFuncAttributeMaxDynamicSharedMemorySize,
                         GEMM_SMEM_BYTES);
    k_gemmA<<<dim3(HH / 64, E_EDGES / 128), 256, GEMM_SMEM_BYTES>>>();

    for (int t = 0; t < T_STEPS; t++) {
        const float* xin = (t & 1) ? px1 : px0;
        float* xout = (t == T_STEPS - 1) ? out : ((t & 1) ? px0 : px1);
        k_msg<<<(E_EDGES * 32) / 256, 256>>>(xin, edges);
        k_gru<<<N_NODES / NPB, 256>>>(xin, xout, W_ih, W_hh, b_ih, b_hh);
    }
}

// round 10
// speedup vs baseline: 1.1892x; 1.0151x over previous
#include <cuda_runtime.h>
#include <cstdint>

#define N_NODES 2000
#define E_EDGES 64000
#define ED_DIM  16
#define ENH_DIM 128
#define H_DIM   64
#define HH      4096   // H*H
#define T_STEPS 8

// ---------------- scratch (device globals; no allocation) ----------------
__device__ float          g_h1 [(size_t)E_EDGES * ENH_DIM];   // 32.8 MB
__device__ unsigned short g_Aq [(size_t)E_EDGES * HH];        // 524 MB, A[e][j*64+i] uint16 fixed-point
__device__ float          g_s  [(size_t)E_EDGES * H_DIM];     // 16.4 MB, per-(edge,j) scale (row max)
__device__ float          g_W2p[(size_t)HH * ENH_DIM];        // W2 permuted+transposed: [c'][k]
__device__ float          g_b2p[HH];
__device__ float          g_m  [N_NODES * H_DIM];
__device__ float          g_x0 [N_NODES * H_DIM];
__device__ float          g_x1 [N_NODES * H_DIM];

// ---------------- f32x2 helpers ----------------
__device__ __forceinline__ unsigned long long ffma2(unsigned long long a,
                                                    unsigned long long b,
                                                    unsigned long long c) {
    unsigned long long d;
    asm("fma.rn.f32x2 %0, %1, %2, %3;" : "=l"(d) : "l"(a), "l"(b), "l"(c));
    return d;
}
__device__ __forceinline__ unsigned long long splat2(float x) {
    unsigned long long d;
    asm("mov.b64 %0, {%1, %1};" : "=l"(d) : "f"(x));
    return d;
}
__device__ __forceinline__ unsigned long long pack2(float lo, float hi) {
    unsigned long long d;
    asm("mov.b64 %0, {%1, %2};" : "=l"(d) : "f"(lo), "f"(hi));
    return d;
}

// ---------------- h1 = relu(ef @ W1 + b1) ----------------
__global__ __launch_bounds__(128) void k_h1(const float* __restrict__ edge_data,
                                            const int*   __restrict__ edges,
                                            const float* __restrict__ W1,
                                            const float* __restrict__ b1) {
    int e = blockIdx.x;
    __shared__ float ef[ED_DIM];
    int src = edges[2 * e], tgt = edges[2 * e + 1];
    if (threadIdx.x < ED_DIM)
        ef[threadIdx.x] = edge_data[((size_t)src * N_NODES + tgt) * ED_DIM + threadIdx.x];
    __syncthreads();
    int u = threadIdx.x;
    float acc = b1[u];
#pragma unroll
    for (int k = 0; k < ED_DIM; k++) acc += ef[k] * W1[k * ENH_DIM + u];
    g_h1[(size_t)e * ENH_DIM + u] = fmaxf(acc, 0.f);
}

// ---------------- permute W2 -> [c'][k] with c' = j*64+i (orig col = i*64+j) ----------------
__global__ void k_permW2(const float* __restrict__ W2, const float* __restrict__ b2) {
    int idx = blockIdx.x * blockDim.x + threadIdx.x;
    if (idx < ENH_DIM * HH) {
        int cp = idx >> 7, k = idx & 127;                // out layout [cp][k]
        int orig = ((cp & 63) << 6) + (cp >> 6);         // i*64 + j
        g_W2p[idx] = W2[(size_t)k * HH + orig];
    }
    if (idx < HH) g_b2p[idx] = b2[((idx & 63) << 6) + (idx >> 6)];
}

// ---------------- A' = relu(h1 @ W2p + b2p) -> uint16 + exact per-(e,j) scale ----------------
// BM=128 (edges), BN=64 (cols = all i for one j), K=128. 128 threads as
// 16(ty) x 8(tx), 8x8 microtile, k-paired f32x2 accumulators. Warp = 4 ty x
// 8 tx, so 'a' LDS is 8-lane broadcast (4 distinct addrs) and 'b' LDS is
// 4-lane broadcast (8 distinct): smem traffic ~1.5 B per FFMA2 -> fma-bound.
// Epilogue: 8-lane shfl max over tx gives exact s[e][j]; q = rne(v*65535/s).
// Grid: x = j (64), y = edge-blocks (500) so a wave shares h1 rows in L2.
#define AS_STRIDE 132
#define GEMM_SMEM_BYTES ((128 * AS_STRIDE + 64 * AS_STRIDE) * 4)

__global__ __launch_bounds__(128, 2) void k_gemmA() {
    extern __shared__ float sh[];
    float* As = sh;                    // [128][132]  (row-major in k)
    float* Bs = sh + 128 * AS_STRIDE;  // [64][132]   (col-major: [c][k])
    const int t = threadIdx.x;
    const int jj = blockIdx.x;
    const int eBase = blockIdx.y * 128;
    const int cBase = jj * 64;

    for (int i = t * 4; i < 128 * 128; i += 512) {
        int r = i >> 7, k = i & 127;
        *reinterpret_cast<float4*>(&As[r * AS_STRIDE + k]) =
            *reinterpret_cast<const float4*>(&g_h1[(size_t)(eBase + r) * ENH_DIM + k]);
    }
    for (int i = t * 4; i < 64 * 128; i += 512) {
        int c = i >> 7, k = i & 127;
        *reinterpret_cast<float4*>(&Bs[c * AS_STRIDE + k]) =
            *reinterpret_cast<const float4*>(&g_W2p[(size_t)(cBase + c) * ENH_DIM + k]);
    }
    __syncthreads();

    const int ty = t >> 3;  // 0..15, rows ty + 16*rr
    const int tx = t & 7;   // 0..7,  cols tx + 8*cc
    unsigned long long acc[8][8];
#pragma unroll
    for (int rr = 0; rr < 8; rr++)
#pragma unroll
        for (int cc = 0; cc < 8; cc++) acc[rr][cc] = 0ull;

#pragma unroll 4
    for (int k = 0; k < 128; k += 2) {
        unsigned long long a[8], b[8];
#pragma unroll
        for (int rr = 0; rr < 8; rr++)
            a[rr] = *reinterpret_cast<const unsigned long long*>(&As[(ty + 16 * rr) * AS_STRIDE + k]);
#pragma unroll
        for (int cc = 0; cc < 8; cc++)
            b[cc] = *reinterpret_cast<const unsigned long long*>(&Bs[(tx + 8 * cc) * AS_STRIDE + k]);
#pragma unroll
        for (int rr = 0; rr < 8; rr++)
#pragma unroll
            for (int cc = 0; cc < 8; cc++)
                acc[rr][cc] = ffma2(a[rr], b[cc], acc[rr][cc]);
    }

    float bb[8];
#pragma unroll
    for (int cc = 0; cc < 8; cc++) bb[cc] = g_b2p[cBase + tx + 8 * cc];

#pragma unroll
    for (int rr = 0; rr < 8; rr++) {
        float v[8];
        float mx = 0.f;
#pragma unroll
        for (int cc = 0; cc < 8; cc++) {
            float2 p = *reinterpret_cast<float2*>(&acc[rr][cc]);
            v[cc] = fmaxf(p.x + p.y + bb[cc], 0.f);
            mx = fmaxf(mx, v[cc]);
        }
        // exact max over the 64 i-columns of this (edge, j) row: reduce over tx
        // (lane = (ty&3)*8 + tx; xor of tx bits stays inside the tx group)
#pragma unroll
        for (int off = 1; off < 8; off <<= 1)
            mx = fmaxf(mx, __shfl_xor_sync(0xffffffffu, mx, off));
        if (tx == 0)
            g_s[(size_t)(eBase + ty + 16 * rr) * H_DIM + jj] = mx;
        float rcp = 65535.f / fmaxf(mx, 1e-30f);
        size_t rowb = (size_t)(eBase + ty + 16 * rr) * HH + (size_t)jj * 64;
#pragma unroll
        for (int cc = 0; cc < 8; cc++)
            g_Aq[rowb + tx + 8 * cc] = (unsigned short)__float2uint_rn(v[cc] * rcp);
    }
}

// ---------------- msg + scatter: warp per edge ----------------
// A stored uint16 as [e][j*64 + i] with scale s[e][j]: lane l accumulates msg
// rows 2l, 2l+1 via coalesced 32-bit ushort2 loads of row j; scaled x[src][j]
// (x_j * s_ej / 65535) broadcast by shfl. fp32 f32x2 accumulate, then atomicAdd.
__global__ __launch_bounds__(256) void k_msg(const float* __restrict__ x,
                                             const int*   __restrict__ edges) {
    int wid = (blockIdx.x * blockDim.x + threadIdx.x) >> 5;
    if (wid >= E_EDGES) return;
    int lane = threadIdx.x & 31;
    int src = edges[2 * wid], tgt = edges[2 * wid + 1];
    const float inv = 1.f / 65535.f;
    float s0 = g_s[(size_t)wid * H_DIM + lane];
    float s1 = g_s[(size_t)wid * H_DIM + 32 + lane];
    float xlo = x[src * H_DIM + lane]      * s0 * inv;
    float xhi = x[src * H_DIM + 32 + lane] * s1 * inv;
    const ushort2* __restrict__ Ap =
        reinterpret_cast<const ushort2*>(g_Aq + (size_t)wid * HH) + lane;

    unsigned long long acc = 0ull;
#pragma unroll
    for (int j = 0; j < H_DIM; j++) {
        float xj = (j < 32) ? __shfl_sync(0xffffffffu, xlo, j)
                            : __shfl_sync(0xffffffffu, xhi, j - 32);
        ushort2 q = Ap[j * 32];
        acc = ffma2(pack2((float)q.x, (float)q.y), splat2(xj), acc);
    }
    float2 mv = *reinterpret_cast<float2*>(&acc);
    int r0 = 2 * lane;
    atomicAdd(&g_m[tgt * H_DIM + r0],     mv.x);
    atomicAdd(&g_m[tgt * H_DIM + r0 + 1], mv.y);
    if (src != tgt) {
        atomicAdd(&g_m[src * H_DIM + r0],     mv.x);
        atomicAdd(&g_m[src * H_DIM + r0 + 1], mv.y);
    }
}

// ---------------- GRU cell: 16 nodes/block, 4 nodes/thread ----------------
#define NPB 16
__global__ __launch_bounds__(256) void k_gru(const float* __restrict__ xin,
                                             float*       __restrict__ xout,
                                             const float* __restrict__ Wih,
                                             const float* __restrict__ Whh,
                                             const float* __restrict__ bih,
                                             const float* __restrict__ bhh) {
    __shared__ float sx[NPB * H_DIM];
    __shared__ float sm[NPB * H_DIM];
    int t = threadIdx.x;
    int base = blockIdx.x * NPB * H_DIM;
    for (int i = t; i < NPB * H_DIM; i += 256) {
        sx[i] = xin[base + i];
        sm[i] = g_m[base + i];
        g_m[base + i] = 0.f;   // reset accumulator for next step / next replay
    }
    __syncthreads();

    int c  = t & 63;
    int ng = t >> 6;  // handles nodes ng*4 .. ng*4+3
    float aR[4], aZ[4], aN[4], hR[4], hZ[4], hN[4];
    float biR = bih[c], biZ = bih[64 + c], biN = bih[128 + c];
    float bhR = bhh[c], bhZ = bhh[64 + c], bhN = bhh[128 + c];
#pragma unroll
    for (int q = 0; q < 4; q++) {
        aR[q] = biR; aZ[q] = biZ; aN[q] = biN;
        hR[q] = bhR; hZ[q] = bhZ; hN[q] = bhN;
    }
#pragma unroll 4
    for (int k = 0; k < H_DIM; k++) {
        float w0 = Wih[k * 192 + c], w1 = Wih[k * 192 + 64 + c], w2 = Wih[k * 192 + 128 + c];
        float v0 = Wih[(64 + k) * 192 + c], v1 = Wih[(64 + k) * 192 + 64 + c], v2 = Wih[(64 + k) * 192 + 128 + c];
        float u0 = Whh[k * 192 + c], u1 = Whh[k * 192 + 64 + c], u2 = Whh[k * 192 + 128 + c];
#pragma unroll
        for (int q = 0; q < 4; q++) {
            float xv = sx[(ng * 4 + q) * H_DIM + k];
            float mv = sm[(ng * 4 + q) * H_DIM + k];
            aR[q] += xv * w0 + mv * v0;
            aZ[q] += xv * w1 + mv * v1;
            aN[q] += xv * w2 + mv * v2;
            hR[q] += xv * u0;
            hZ[q] += xv * u1;
            hN[q] += xv * u2;
        }
    }
#pragma unroll
    for (int q = 0; q < 4; q++) {
        float r = 1.f / (1.f + expf(-(aR[q] + hR[q])));
        float z = 1.f / (1.f + expf(-(aZ[q] + hZ[q])));
        float n = tanhf(aN[q] + r * hN[q]);
        float h = sx[(ng * 4 + q) * H_DIM + c];
        xout[base + (ng * 4 + q) * H_DIM + c] = (1.f - z) * n + z * h;
    }
}

// ---------------- launch ----------------
extern "C" void kernel_launch(void* const* d_in, const int* in_sizes, int n_in,
                              void* d_out, int out_size) {
    const float* x         = (const float*)d_in[0];
    const float* edge_data = (const float*)d_in[2];
    const int*   edges     = (const int*)  d_in[3];
    const float* W1        = (const float*)d_in[5];
    const float* b1        = (const float*)d_in[6];
    const float* W2        = (const float*)d_in[7];
    const float* b2        = (const float*)d_in[8];
    const float* W_ih      = (const float*)d_in[9];
    const float* W_hh      = (const float*)d_in[10];
    const float* b_ih      = (const float*)d_in[11];
    const float* b_hh      = (const float*)d_in[12];
    float* out = (float*)d_out;

    float *px0 = nullptr, *px1 = nullptr, *pm = nullptr;
    cudaGetSymbolAddress((void**)&px0, g_x0);
    cudaGetSymbolAddress((void**)&px1, g_x1);
    cudaGetSymbolAddress((void**)&pm,  g_m);

    cudaMemcpyAsync(px0, x, (size_t)N_NODES * H_DIM * sizeof(float),
                    cudaMemcpyDeviceToDevice, 0);
    cudaMemsetAsync(pm, 0, (size_t)N_NODES * H_DIM * sizeof(float), 0);

    k_h1<<<E_EDGES, 128>>>(edge_data, edges, W1, b1);
    k_permW2<<<(ENH_DIM * HH + 255) / 256, 256>>>(W2, b2);

    cudaFuncSetAttribute(k_gemmA, cudaFuncAttributeMaxDynamicSharedMemorySize,
                         GEMM_SMEM_BYTES);
    k_gemmA<<<dim3(H_DIM, E_EDGES / 128), 128, GEMM_SMEM_BYTES>>>();

    for (int t = 0; t < T_STEPS; t++) {
        const float* xin = (t & 1) ? px1 : px0;
        float* xout = (t == T_STEPS - 1) ? out : ((t & 1) ? px0 : px1);
        k_msg<<<(E_EDGES * 32) / 256, 256>>>(xin, edges);
        k_gru<<<N_NODES / NPB, 256>>>(xin, xout, W_ih, W_hh, b_ih, b_hh);
    }
}

// round 14
// speedup vs baseline: 1.3237x; 1.1131x over previous
#include <cuda_runtime.h>
#include <cuda_bf16.h>
#include <cstdint>

#define N_NODES 2000
#define E_EDGES 64000
#define ED_DIM  16
#define ENH_DIM 128
#define H_DIM   64
#define HH      4096   // H*H
#define T_STEPS 8

// ---------------- scratch (device globals; no allocation) ----------------
__device__ __nv_bfloat16 g_h1hi [(size_t)E_EDGES * ENH_DIM];  // 16.4 MB
__device__ __nv_bfloat16 g_h1lo [(size_t)E_EDGES * ENH_DIM];  // 16.4 MB
__device__ __nv_bfloat16 g_W2phi[(size_t)HH * ENH_DIM];       // 1 MB  [c'][k]
__device__ __nv_bfloat16 g_W2plo[(size_t)HH * ENH_DIM];       // 1 MB
__device__ float          g_b2p [HH];
__device__ unsigned short g_Aq [(size_t)E_EDGES * HH];        // 524 MB, A[e][j*64+i] uint16
__device__ float          g_s  [(size_t)E_EDGES * H_DIM];     // 16.4 MB, per-(e,j) scale
__device__ float          g_m  [N_NODES * H_DIM];
__device__ float          g_x0 [N_NODES * H_DIM];
__device__ float          g_x1 [N_NODES * H_DIM];

// ---------------- f32x2 helpers ----------------
__device__ __forceinline__ unsigned long long ffma2(unsigned long long a,
                                                    unsigned long long b,
                                                    unsigned long long c) {
    unsigned long long d;
    asm("fma.rn.f32x2 %0, %1, %2, %3;" : "=l"(d) : "l"(a), "l"(b), "l"(c));
    return d;
}
__device__ __forceinline__ unsigned long long splat2(float x) {
    unsigned long long d;
    asm("mov.b64 %0, {%1, %1};" : "=l"(d) : "f"(x));
    return d;
}
__device__ __forceinline__ unsigned long long pack2(float lo, float hi) {
    unsigned long long d;
    asm("mov.b64 %0, {%1, %2};" : "=l"(d) : "f"(lo), "f"(hi));
    return d;
}
__device__ __forceinline__ uint32_t smem_u32(const void* p) {
    uint32_t a;
    asm("{ .reg .u64 t; cvta.to.shared.u64 t, %1; cvt.u32.u64 %0, t; }" : "=r"(a) : "l"(p));
    return a;
}

// ---------------- mma.sync plumbing (family-common HMMA path) ----------------
__device__ __forceinline__ void ldsm_x4(uint32_t& a0, uint32_t& a1, uint32_t& a2,
                                        uint32_t& a3, uint32_t addr) {
    asm volatile("ldmatrix.sync.aligned.m8n8.x4.shared.b16 {%0,%1,%2,%3}, [%4];"
                 : "=r"(a0), "=r"(a1), "=r"(a2), "=r"(a3) : "r"(addr));
}
__device__ __forceinline__ void ldsm_x2(uint32_t& b0, uint32_t& b1, uint32_t addr) {
    asm volatile("ldmatrix.sync.aligned.m8n8.x2.shared.b16 {%0,%1}, [%2];"
                 : "=r"(b0), "=r"(b1) : "r"(addr));
}
__device__ __forceinline__ void mma_bf16(float* c, const uint32_t* a, const uint32_t* b) {
    asm volatile(
        "mma.sync.aligned.m16n8k16.row.col.f32.bf16.bf16.f32 "
        "{%0,%1,%2,%3}, {%4,%5,%6,%7}, {%8,%9}, {%0,%1,%2,%3};"
        : "+f"(c[0]), "+f"(c[1]), "+f"(c[2]), "+f"(c[3])
        : "r"(a[0]), "r"(a[1]), "r"(a[2]), "r"(a[3]), "r"(b[0]), "r"(b[1]));
}

// ---------------- h1 = relu(ef @ W1 + b1), split bf16 hi/lo ----------------
__global__ __launch_bounds__(128) void k_h1(const float* __restrict__ edge_data,
                                            const int*   __restrict__ edges,
                                            const float* __restrict__ W1,
                                            const float* __restrict__ b1) {
    int e = blockIdx.x;
    __shared__ float ef[ED_DIM];
    int src = edges[2 * e], tgt = edges[2 * e + 1];
    if (threadIdx.x < ED_DIM)
        ef[threadIdx.x] = edge_data[((size_t)src * N_NODES + tgt) * ED_DIM + threadIdx.x];
    __syncthreads();
    int u = threadIdx.x;
    float acc = b1[u];
#pragma unroll
    for (int k = 0; k < ED_DIM; k++) acc += ef[k] * W1[k * ENH_DIM + u];
    float v = fmaxf(acc, 0.f);
    __nv_bfloat16 hi = __float2bfloat16(v);
    g_h1hi[(size_t)e * ENH_DIM + u] = hi;
    g_h1lo[(size_t)e * ENH_DIM + u] = __float2bfloat16(v - __bfloat162float(hi));
}

// ---------------- W2 -> [c'][k] split bf16, c' = j*64+i (orig col = i*64+j) ----------------
__global__ void k_permW2(const float* __restrict__ W2, const float* __restrict__ b2) {
    int idx = blockIdx.x * blockDim.x + threadIdx.x;
    if (idx < ENH_DIM * HH) {
        int cp = idx >> 7, k = idx & 127;
        int orig = ((cp & 63) << 6) + (cp >> 6);
        float w = W2[(size_t)k * HH + orig];
        __nv_bfloat16 hi = __float2bfloat16(w);
        g_W2phi[idx] = hi;
        g_W2plo[idx] = __float2bfloat16(w - __bfloat162float(hi));
    }
    if (idx < HH) g_b2p[idx] = b2[((idx & 63) << 6) + (idx >> 6)];
}

// ---------------- HMMA GEMM: A[e][c'] = relu(h1 @ W2p + b2p) -> uint16 + scale ----------------
// Tile: BM=128 edges x BN=64 cols (one j) x K=128. 4 warps; warp w owns rows
// [32w, 32w+32) x all 64 cols = 2 x 8 m16n8k16 fragments. bf16 hi/lo 3-product
// split (hi*hi + hi*lo + lo*hi), fp32 accumulators. Rows padded to 136 bf16
// (272 B) so LDSM's 8 row-pointers land in distinct bank groups.
// Grid: x = j (64), y = edge-blocks (500) -> wave shares h1 rows in L2.
#define ROW_B 272                       // padded row stride in bytes (136 bf16)
#define SM_AHI 0
#define SM_ALO (SM_AHI + 128 * ROW_B)   // 34816
#define SM_BHI (SM_ALO + 128 * ROW_B)   // 69632
#define SM_BLO (SM_BHI + 64 * ROW_B)    // 87040
#define SM_BIAS (SM_BLO + 64 * ROW_B)   // 104448
#define GEMM_SMEM_BYTES (SM_BIAS + 256)

__global__ __launch_bounds__(128, 2) void k_gemmA() {
    extern __shared__ char smem[];
    const uint32_t sbase = smem_u32(smem);
    const int t = threadIdx.x;
    const int w = t >> 5, l = t & 31;
    const int jj = blockIdx.x;
    const int eBase = blockIdx.y * 128;
    const int cBase = jj * 64;
    float* sbias = reinterpret_cast<float*>(smem + SM_BIAS);

    // ---- load tiles: A (128 rows) and B (64 rows), hi+lo, 8 bf16 per uint4 ----
    for (int i = t; i < 128 * 16; i += 128) {
        int r = i >> 4, c8 = (i & 15) << 3;
        int dst = r * ROW_B + c8 * 2;
        const size_t srcoff = (size_t)(eBase + r) * ENH_DIM + c8;
        *reinterpret_cast<uint4*>(smem + SM_AHI + dst) =
            *reinterpret_cast<const uint4*>(g_h1hi + srcoff);
        *reinterpret_cast<uint4*>(smem + SM_ALO + dst) =
            *reinterpret_cast<const uint4*>(g_h1lo + srcoff);
    }
    for (int i = t; i < 64 * 16; i += 128) {
        int r = i >> 4, c8 = (i & 15) << 3;
        int dst = r * ROW_B + c8 * 2;
        const size_t srcoff = (size_t)(cBase + r) * ENH_DIM + c8;
        *reinterpret_cast<uint4*>(smem + SM_BHI + dst) =
            *reinterpret_cast<const uint4*>(g_W2phi + srcoff);
        *reinterpret_cast<uint4*>(smem + SM_BLO + dst) =
            *reinterpret_cast<const uint4*>(g_W2plo + srcoff);
    }
    if (t < 64) sbias[t] = g_b2p[cBase + t];
    __syncthreads();

    // ---- mainloop ----
    float acc[2][8][4];
#pragma unroll
    for (int mi = 0; mi < 2; mi++)
#pragma unroll
        for (int ni = 0; ni < 8; ni++)
#pragma unroll
            for (int v = 0; v < 4; v++) acc[mi][ni][v] = 0.f;

    // per-lane ldmatrix address components (byte offsets within a tile)
    const uint32_t aRowOff = (uint32_t)(((l & 15) + w * 32) * ROW_B + ((l >> 4) << 3) * 2);
    const uint32_t bRowOff = (uint32_t)((l & 7) * ROW_B + (((l >> 3) & 1) << 3) * 2);

    const uint32_t aTile[3] = {sbase + SM_AHI, sbase + SM_AHI, sbase + SM_ALO};
    const uint32_t bTile[3] = {sbase + SM_BHI, sbase + SM_BLO, sbase + SM_BHI};

#pragma unroll
    for (int pp = 0; pp < 3; pp++) {
        const uint32_t aBase = aTile[pp] + aRowOff;
        const uint32_t bBase = bTile[pp] + bRowOff;
#pragma unroll
        for (int kk = 0; kk < 128; kk += 16) {
            uint32_t a[2][4], b[8][2];
#pragma unroll
            for (int mi = 0; mi < 2; mi++)
                ldsm_x4(a[mi][0], a[mi][1], a[mi][2], a[mi][3],
                        aBase + (uint32_t)(mi * 16 * ROW_B + kk * 2));
#pragma unroll
            for (int ni = 0; ni < 8; ni++)
                ldsm_x2(b[ni][0], b[ni][1],
                        bBase + (uint32_t)(ni * 8 * ROW_B + kk * 2));
#pragma unroll
            for (int mi = 0; mi < 2; mi++)
#pragma unroll
                for (int ni = 0; ni < 8; ni++)
                    mma_bf16(acc[mi][ni], a[mi], b[ni]);
        }
    }

    // ---- epilogue: relu + exact per-(e,j) row max + uint16 quant ----
    // frag layout: lane l holds rows (mi*16 + l/4) and (+8), cols ni*8 + 2*(l%4), +1
    const int qrow = l >> 2, quad = l & 3;
    float bias0[8], bias1[8];
#pragma unroll
    for (int ni = 0; ni < 8; ni++) {
        bias0[ni] = sbias[ni * 8 + 2 * quad];
        bias1[ni] = sbias[ni * 8 + 2 * quad + 1];
    }
#pragma unroll
    for (int mi = 0; mi < 2; mi++) {
#pragma unroll
        for (int half = 0; half < 2; half++) {
            int r = w * 32 + mi * 16 + half * 8 + qrow;
            int e = eBase + r;
            float v0[8], v1[8];
            float mx = 0.f;
#pragma unroll
            for (int ni = 0; ni < 8; ni++) {
                v0[ni] = fmaxf(acc[mi][ni][half * 2 + 0] + bias0[ni], 0.f);
                v1[ni] = fmaxf(acc[mi][ni][half * 2 + 1] + bias1[ni], 0.f);
                mx = fmaxf(mx, fmaxf(v0[ni], v1[ni]));
            }
            // full row max: reduce over the 4 quad lanes (same qrow)
            mx = fmaxf(mx, __shfl_xor_sync(0xffffffffu, mx, 1));
            mx = fmaxf(mx, __shfl_xor_sync(0xffffffffu, mx, 2));
            if (quad == 0)
                g_s[(size_t)e * H_DIM + jj] = mx;
            float rcp = 65535.f / fmaxf(mx, 1e-30f);
            uint32_t* Arow = reinterpret_cast<uint32_t*>(
                g_Aq + (size_t)e * HH + (size_t)jj * 64);
#pragma unroll
            for (int ni = 0; ni < 8; ni++) {
                uint32_t u0 = __float2uint_rn(v0[ni] * rcp);
                uint32_t u1 = __float2uint_rn(v1[ni] * rcp);
                Arow[(ni * 8 + 2 * quad) >> 1] = (u0 & 0xFFFFu) | (u1 << 16);
            }
        }
    }
}

// ---------------- msg + scatter: warp per edge ----------------
// A stored uint16 as [e][j*64 + i] with scale s[e][j]: lane l accumulates msg
// rows 2l, 2l+1 via coalesced ushort2 loads of row j. Unroll 4 with two f32x2
// accumulator chains to keep 4 loads in flight (MLP).
__global__ __launch_bounds__(256) void k_msg(const float* __restrict__ x,
                                             const int*   __restrict__ edges) {
    int wid = (blockIdx.x * blockDim.x + threadIdx.x) >> 5;
    if (wid >= E_EDGES) return;
    int lane = threadIdx.x & 31;
    int src = edges[2 * wid], tgt = edges[2 * wid + 1];
    const float inv = 1.f / 65535.f;
    float s0 = g_s[(size_t)wid * H_DIM + lane];
    float s1 = g_s[(size_t)wid * H_DIM + 32 + lane];
    float xlo = x[src * H_DIM + lane]      * s0 * inv;
    float xhi = x[src * H_DIM + 32 + lane] * s1 * inv;
    const ushort2* __restrict__ Ap =
        reinterpret_cast<const ushort2*>(g_Aq + (size_t)wid * HH) + lane;

    unsigned long long acc0 = 0ull, acc1 = 0ull;
#pragma unroll
    for (int jb = 0; jb < H_DIM; jb += 4) {
        ushort2 q[4];
#pragma unroll
        for (int u = 0; u < 4; u++) q[u] = Ap[(jb + u) * 32];
#pragma unroll
        for (int u = 0; u < 4; u++) {
            int j = jb + u;
            float xj = (j < 32) ? __shfl_sync(0xffffffffu, xlo, j)
                                : __shfl_sync(0xffffffffu, xhi, j - 32);
            if (u & 1) acc1 = ffma2(pack2((float)q[u].x, (float)q[u].y), splat2(xj), acc1);
            else       acc0 = ffma2(pack2((float)q[u].x, (float)q[u].y), splat2(xj), acc0);
        }
    }
    float2 m0 = *reinterpret_cast<float2*>(&acc0);
    float2 m1 = *reinterpret_cast<float2*>(&acc1);
    float2 mv = make_float2(m0.x + m1.x, m0.y + m1.y);
    int r0 = 2 * lane;
    atomicAdd(&g_m[tgt * H_DIM + r0],     mv.x);
    atomicAdd(&g_m[tgt * H_DIM + r0 + 1], mv.y);
    if (src != tgt) {
        atomicAdd(&g_m[src * H_DIM + r0],     mv.x);
        atomicAdd(&g_m[src * H_DIM + r0 + 1], mv.y);
    }
}

// ---------------- GRU cell: 16 nodes/block, 4 nodes/thread ----------------
#define NPB 16
__global__ __launch_bounds__(256) void k_gru(const float* __restrict__ xin,
                                             float*       __restrict__ xout,
                                             const float* __restrict__ Wih,
                                             const float* __restrict__ Whh,
                                             const float* __restrict__ bih,
                                             const float* __restrict__ bhh) {
    __shared__ float sx[NPB * H_DIM];
    __shared__ float sm[NPB * H_DIM];
    int t = threadIdx.x;
    int base = blockIdx.x * NPB * H_DIM;
    for (int i = t; i < NPB * H_DIM; i += 256) {
        sx[i] = xin[base + i];
        sm[i] = g_m[base + i];
        g_m[base + i] = 0.f;   // reset accumulator for next step / next replay
    }
    __syncthreads();

    int c  = t & 63;
    int ng = t >> 6;  // handles nodes ng*4 .. ng*4+3
    float aR[4], aZ[4], aN[4], hR[4], hZ[4], hN[4];
    float biR = bih[c], biZ = bih[64 + c], biN = bih[128 + c];
    float bhR = bhh[c], bhZ = bhh[64 + c], bhN = bhh[128 + c];
#pragma unroll
    for (int q = 0; q < 4; q++) {
        aR[q] = biR; aZ[q] = biZ; aN[q] = biN;
        hR[q] = bhR; hZ[q] = bhZ; hN[q] = bhN;
    }
#pragma unroll 4
    for (int k = 0; k < H_DIM; k++) {
        float w0 = Wih[k * 192 + c], w1 = Wih[k * 192 + 64 + c], w2 = Wih[k * 192 + 128 + c];
        float v0 = Wih[(64 + k) * 192 + c], v1 = Wih[(64 + k) * 192 + 64 + c], v2 = Wih[(64 + k) * 192 + 128 + c];
        float u0 = Whh[k * 192 + c], u1 = Whh[k * 192 + 64 + c], u2 = Whh[k * 192 + 128 + c];
#pragma unroll
        for (int q = 0; q < 4; q++) {
            float xv = sx[(ng * 4 + q) * H_DIM + k];
            float mv = sm[(ng * 4 + q) * H_DIM + k];
            aR[q] += xv * w0 + mv * v0;
            aZ[q] += xv * w1 + mv * v1;
            aN[q] += xv * w2 + mv * v2;
            hR[q] += xv * u0;
            hZ[q] += xv * u1;
            hN[q] += xv * u2;
        }
    }
#pragma unroll
    for (int q = 0; q < 4; q++) {
        float r = 1.f / (1.f + expf(-(aR[q] + hR[q])));
        float z = 1.f / (1.f + expf(-(aZ[q] + hZ[q])));
        float n = tanhf(aN[q] + r * hN[q]);
        float h = sx[(ng * 4 + q) * H_DIM + c];
        xout[base + (ng * 4 + q) * H_DIM + c] = (1.f - z) * n + z * h;
    }
}

// ---------------- launch ----------------
extern "C" void kernel_launch(void* const* d_in, const int* in_sizes, int n_in,
                              void* d_out, int out_size) {
    const float* x         = (const float*)d_in[0];
    const float* edge_data = (const float*)d_in[2];
    const int*   edges     = (const int*)  d_in[3];
    const float* W1        = (const float*)d_in[5];
    const float* b1        = (const float*)d_in[6];
    const float* W2        = (const float*)d_in[7];
    const float* b2        = (const float*)d_in[8];
    const float* W_ih      = (const float*)d_in[9];
    const float* W_hh      = (const float*)d_in[10];
    const float* b_ih      = (const float*)d_in[11];
    const float* b_hh      = (const float*)d_in[12];
    float* out = (float*)d_out;

    float *px0 = nullptr, *px1 = nullptr, *pm = nullptr;
    cudaGetSymbolAddress((void**)&px0, g_x0);
    cudaGetSymbolAddress((void**)&px1, g_x1);
    cudaGetSymbolAddress((void**)&pm,  g_m);

    cudaMemcpyAsync(px0, x, (size_t)N_NODES * H_DIM * sizeof(float),
                    cudaMemcpyDeviceToDevice, 0);
    cudaMemsetAsync(pm, 0, (size_t)N_NODES * H_DIM * sizeof(float), 0);

    k_h1<<<E_EDGES, 128>>>(edge_data, edges, W1, b1);
    k_permW2<<<(ENH_DIM * HH + 255) / 256, 256>>>(W2, b2);

    cudaFuncSetAttribute(k_gemmA, cudaFuncAttributeMaxDynamicSharedMemorySize,
                         GEMM_SMEM_BYTES);
    k_gemmA<<<dim3(H_DIM, E_EDGES / 128), 128, GEMM_SMEM_BYTES>>>();

    for (int t = 0; t < T_STEPS; t++) {
        const float* xin = (t & 1) ? px1 : px0;
        float* xout = (t == T_STEPS - 1) ? out : ((t & 1) ? px0 : px1);
        k_msg<<<(E_EDGES * 32) / 256, 256>>>(xin, edges);
        k_gru<<<N_NODES / NPB, 256>>>(xin, xout, W_ih, W_hh, b_ih, b_hh);
    }
}

// round 17
// speedup vs baseline: 1.4352x; 1.0842x over previous
#include <cuda_runtime.h>
#include <cuda_bf16.h>
#include <cstdint>

#define N_NODES 2000
#define E_EDGES 64000
#define ED_DIM  16
#define ENH_DIM 128
#define H_DIM   64
#define HH      4096   // H*H
#define T_STEPS 8

// ---------------- scratch (device globals; no allocation) ----------------
__device__ __nv_bfloat16 g_h1hi [(size_t)E_EDGES * ENH_DIM];  // 16.4 MB
__device__ __nv_bfloat16 g_h1lo [(size_t)E_EDGES * ENH_DIM];  // 16.4 MB
__device__ __nv_bfloat16 g_W2phi[(size_t)HH * ENH_DIM];       // 1 MB  [c'][k]
__device__ __nv_bfloat16 g_W2plo[(size_t)HH * ENH_DIM];       // 1 MB
__device__ float          g_b2p [HH];
__device__ unsigned short g_Aq [(size_t)E_EDGES * HH];        // 524 MB, A[e][j*64+i] uint16
__device__ float          g_s  [(size_t)E_EDGES * H_DIM];     // 16.4 MB, per-(e,j) scale
__device__ float          g_m  [N_NODES * H_DIM];
__device__ float          g_x0 [N_NODES * H_DIM];
__device__ float          g_x1 [N_NODES * H_DIM];

// ---------------- f32x2 helpers ----------------
__device__ __forceinline__ unsigned long long ffma2(unsigned long long a,
                                                    unsigned long long b,
                                                    unsigned long long c) {
    unsigned long long d;
    asm("fma.rn.f32x2 %0, %1, %2, %3;" : "=l"(d) : "l"(a), "l"(b), "l"(c));
    return d;
}
__device__ __forceinline__ unsigned long long splat2(float x) {
    unsigned long long d;
    asm("mov.b64 %0, {%1, %1};" : "=l"(d) : "f"(x));
    return d;
}
__device__ __forceinline__ unsigned long long pack2(float lo, float hi) {
    unsigned long long d;
    asm("mov.b64 %0, {%1, %2};" : "=l"(d) : "f"(lo), "f"(hi));
    return d;
}
__device__ __forceinline__ uint32_t smem_u32(const void* p) {
    uint32_t a;
    asm("{ .reg .u64 t; cvta.to.shared.u64 t, %1; cvt.u32.u64 %0, t; }" : "=r"(a) : "l"(p));
    return a;
}

// ---------------- mma.sync plumbing (family-common HMMA path) ----------------
__device__ __forceinline__ void ldsm_x4(uint32_t& a0, uint32_t& a1, uint32_t& a2,
                                        uint32_t& a3, uint32_t addr) {
    asm volatile("ldmatrix.sync.aligned.m8n8.x4.shared.b16 {%0,%1,%2,%3}, [%4];"
                 : "=r"(a0), "=r"(a1), "=r"(a2), "=r"(a3) : "r"(addr));
}
__device__ __forceinline__ void mma_bf16(float* c, const uint32_t* a, const uint32_t* b) {
    asm volatile(
        "mma.sync.aligned.m16n8k16.row.col.f32.bf16.bf16.f32 "
        "{%0,%1,%2,%3}, {%4,%5,%6,%7}, {%8,%9}, {%0,%1,%2,%3};"
        : "+f"(c[0]), "+f"(c[1]), "+f"(c[2]), "+f"(c[3])
        : "r"(a[0]), "r"(a[1]), "r"(a[2]), "r"(a[3]), "r"(b[0]), "r"(b[1]));
}

// ---------------- h1 = relu(ef @ W1 + b1), split bf16 hi/lo ----------------
__global__ __launch_bounds__(128) void k_h1(const float* __restrict__ edge_data,
                                            const int*   __restrict__ edges,
                                            const float* __restrict__ W1,
                                            const float* __restrict__ b1) {
    int e = blockIdx.x;
    __shared__ float ef[ED_DIM];
    int src = edges[2 * e], tgt = edges[2 * e + 1];
    if (threadIdx.x < ED_DIM)
        ef[threadIdx.x] = edge_data[((size_t)src * N_NODES + tgt) * ED_DIM + threadIdx.x];
    __syncthreads();
    int u = threadIdx.x;
    float acc = b1[u];
#pragma unroll
    for (int k = 0; k < ED_DIM; k++) acc += ef[k] * W1[k * ENH_DIM + u];
    float v = fmaxf(acc, 0.f);
    __nv_bfloat16 hi = __float2bfloat16(v);
    g_h1hi[(size_t)e * ENH_DIM + u] = hi;
    g_h1lo[(size_t)e * ENH_DIM + u] = __float2bfloat16(v - __bfloat162float(hi));
}

// ---------------- W2 -> [c'][k] split bf16, c' = j*64+i (orig col = i*64+j) ----------------
__global__ void k_permW2(const float* __restrict__ W2, const float* __restrict__ b2) {
    int idx = blockIdx.x * blockDim.x + threadIdx.x;
    if (idx < ENH_DIM * HH) {
        int cp = idx >> 7, k = idx & 127;
        int orig = ((cp & 63) << 6) + (cp >> 6);
        float w = W2[(size_t)k * HH + orig];
        __nv_bfloat16 hi = __float2bfloat16(w);
        g_W2phi[idx] = hi;
        g_W2plo[idx] = __float2bfloat16(w - __bfloat162float(hi));
    }
    if (idx < HH) g_b2p[idx] = b2[((idx & 63) << 6) + (idx >> 6)];
}

// ---------------- HMMA GEMM: A[e][c'] = relu(h1 @ W2p + b2p) -> uint16 + scale ----------------
// Tile: BM=128 edges x BN=64 cols (one j) x K=128. 8 warps; warp w owns rows
// [16w, 16w+16) x all 64 cols = 8 m16n8k16 fragments. bf16 hi/lo 3-product
// split, fp32 accumulators. LDSM per k-iter: 1 x4 (A) + 4 x4 (B, two n8 frags
// each) = 5 LDSM / 8 HMMA. 2 CTAs/SM -> 16 warps/SM for latency hiding.
// Rows padded to 136 bf16 (272 B) for conflict-free LDSM.
// Grid: x = j (64), y = edge-blocks (500) -> wave shares h1 rows in L2.
#define ROW_B 272                       // padded row stride in bytes (136 bf16)
#define SM_AHI 0
#define SM_ALO (SM_AHI + 128 * ROW_B)   // 34816
#define SM_BHI (SM_ALO + 128 * ROW_B)   // 69632
#define SM_BLO (SM_BHI + 64 * ROW_B)    // 87040
#define SM_BIAS (SM_BLO + 64 * ROW_B)   // 104448
#define GEMM_SMEM_BYTES (SM_BIAS + 256)

__global__ __launch_bounds__(256, 2) void k_gemmA() {
    extern __shared__ char smem[];
    const uint32_t sbase = smem_u32(smem);
    const int t = threadIdx.x;
    const int w = t >> 5, l = t & 31;
    const int jj = blockIdx.x;
    const int eBase = blockIdx.y * 128;
    const int cBase = jj * 64;
    float* sbias = reinterpret_cast<float*>(smem + SM_BIAS);

    // ---- load tiles: A (128 rows) and B (64 rows), hi+lo, 8 bf16 per uint4 ----
    for (int i = t; i < 128 * 16; i += 256) {
        int r = i >> 4, c8 = (i & 15) << 3;
        int dst = r * ROW_B + c8 * 2;
        const size_t srcoff = (size_t)(eBase + r) * ENH_DIM + c8;
        *reinterpret_cast<uint4*>(smem + SM_AHI + dst) =
            *reinterpret_cast<const uint4*>(g_h1hi + srcoff);
        *reinterpret_cast<uint4*>(smem + SM_ALO + dst) =
            *reinterpret_cast<const uint4*>(g_h1lo + srcoff);
    }
    for (int i = t; i < 64 * 16; i += 256) {
        int r = i >> 4, c8 = (i & 15) << 3;
        int dst = r * ROW_B + c8 * 2;
        const size_t srcoff = (size_t)(cBase + r) * ENH_DIM + c8;
        *reinterpret_cast<uint4*>(smem + SM_BHI + dst) =
            *reinterpret_cast<const uint4*>(g_W2phi + srcoff);
        *reinterpret_cast<uint4*>(smem + SM_BLO + dst) =
            *reinterpret_cast<const uint4*>(g_W2plo + srcoff);
    }
    if (t < 64) sbias[t] = g_b2p[cBase + t];
    __syncthreads();

    // ---- mainloop ----
    float acc[8][4];
#pragma unroll
    for (int ni = 0; ni < 8; ni++)
#pragma unroll
        for (int v = 0; v < 4; v++) acc[ni][v] = 0.f;

    // A ldsm x4 (m16 x k16): lane 0-15 -> row (l&15), k-half 0; 16-31 -> k-half 1
    const uint32_t aRowOff = (uint32_t)(((l & 15) + w * 16) * ROW_B + (l >> 4) * 16);
    // B ldsm x4 (n16 x k16): matrices = (n0-7,k0) (n0-7,k8) (n8-15,k0) (n8-15,k8)
    const uint32_t bRowOff = (uint32_t)(((l & 7) + ((l >> 4) << 3)) * ROW_B
                                        + ((l >> 3) & 1) * 16);

    const uint32_t aTile[3] = {sbase + SM_AHI, sbase + SM_AHI, sbase + SM_ALO};
    const uint32_t bTile[3] = {sbase + SM_BHI, sbase + SM_BLO, sbase + SM_BHI};

#pragma unroll
    for (int pp = 0; pp < 3; pp++) {
        const uint32_t aBase = aTile[pp] + aRowOff;
        const uint32_t bBase = bTile[pp] + bRowOff;
#pragma unroll
        for (int kk = 0; kk < 128; kk += 16) {
            uint32_t a[4], b[8][2];
            ldsm_x4(a[0], a[1], a[2], a[3], aBase + (uint32_t)(kk * 2));
#pragma unroll
            for (int np = 0; np < 4; np++) {
                uint32_t r0, r1, r2, r3;
                ldsm_x4(r0, r1, r2, r3,
                        bBase + (uint32_t)(np * 16 * ROW_B + kk * 2));
                b[2 * np][0] = r0; b[2 * np][1] = r1;
                b[2 * np + 1][0] = r2; b[2 * np + 1][1] = r3;
            }
#pragma unroll
            for (int ni = 0; ni < 8; ni++)
                mma_bf16(acc[ni], a, b[ni]);
        }
    }

    // ---- epilogue: relu + exact per-(e,j) row max + uint16 quant ----
    // frag layout: lane l holds rows (w*16 + l/4) and (+8), cols ni*8 + 2*(l%4), +1
    const int qrow = l >> 2, quad = l & 3;
    float bias0[8], bias1[8];
#pragma unroll
    for (int ni = 0; ni < 8; ni++) {
        bias0[ni] = sbias[ni * 8 + 2 * quad];
        bias1[ni] = sbias[ni * 8 + 2 * quad + 1];
    }
#pragma unroll
    for (int half = 0; half < 2; half++) {
        int e = eBase + w * 16 + half * 8 + qrow;
        float v0[8], v1[8];
        float mx = 0.f;
#pragma unroll
        for (int ni = 0; ni < 8; ni++) {
            v0[ni] = fmaxf(acc[ni][half * 2 + 0] + bias0[ni], 0.f);
            v1[ni] = fmaxf(acc[ni][half * 2 + 1] + bias1[ni], 0.f);
            mx = fmaxf(mx, fmaxf(v0[ni], v1[ni]));
        }
        // full row max: reduce over the 4 quad lanes (same row)
        mx = fmaxf(mx, __shfl_xor_sync(0xffffffffu, mx, 1));
        mx = fmaxf(mx, __shfl_xor_sync(0xffffffffu, mx, 2));
        if (quad == 0)
            g_s[(size_t)e * H_DIM + jj] = mx;
        float rcp = 65535.f / fmaxf(mx, 1e-30f);
        uint32_t* Arow = reinterpret_cast<uint32_t*>(
            g_Aq + (size_t)e * HH + (size_t)jj * 64);
#pragma unroll
        for (int ni = 0; ni < 8; ni++) {
            uint32_t u0 = __float2uint_rn(v0[ni] * rcp);
            uint32_t u1 = __float2uint_rn(v1[ni] * rcp);
            Arow[(ni * 8 + 2 * quad) >> 1] = (u0 & 0xFFFFu) | (u1 << 16);
        }
    }
}

// ---------------- msg + scatter: warp per edge ----------------
// A stored uint16 as [e][j*64 + i] with scale s[e][j]: lane l accumulates msg
// rows 2l, 2l+1 via coalesced ushort2 loads of row j. Unroll 4 with two f32x2
// accumulator chains to keep 4 loads in flight (MLP).
__global__ __launch_bounds__(256) void k_msg(const float* __restrict__ x,
                                             const int*   __restrict__ edges) {
    int wid = (blockIdx.x * blockDim.x + threadIdx.x) >> 5;
    if (wid >= E_EDGES) return;
    int lane = threadIdx.x & 31;
    int src = edges[2 * wid], tgt = edges[2 * wid + 1];
    const float inv = 1.f / 65535.f;
    float s0 = g_s[(size_t)wid * H_DIM + lane];
    float s1 = g_s[(size_t)wid * H_DIM + 32 + lane];
    float xlo = x[src * H_DIM + lane]      * s0 * inv;
    float xhi = x[src * H_DIM + 32 + lane] * s1 * inv;
    const ushort2* __restrict__ Ap =
        reinterpret_cast<const ushort2*>(g_Aq + (size_t)wid * HH) + lane;

    unsigned long long acc0 = 0ull, acc1 = 0ull;
#pragma unroll
    for (int jb = 0; jb < H_DIM; jb += 4) {
        ushort2 q[4];
#pragma unroll
        for (int u = 0; u < 4; u++) q[u] = Ap[(jb + u) * 32];
#pragma unroll
        for (int u = 0; u < 4; u++) {
            int j = jb + u;
            float xj = (j < 32) ? __shfl_sync(0xffffffffu, xlo, j)
                                : __shfl_sync(0xffffffffu, xhi, j - 32);
            if (u & 1) acc1 = ffma2(pack2((float)q[u].x, (float)q[u].y), splat2(xj), acc1);
            else       acc0 = ffma2(pack2((float)q[u].x, (float)q[u].y), splat2(xj), acc0);
        }
    }
    float2 m0 = *reinterpret_cast<float2*>(&acc0);
    float2 m1 = *reinterpret_cast<float2*>(&acc1);
    float2 mv = make_float2(m0.x + m1.x, m0.y + m1.y);
    int r0 = 2 * lane;
    atomicAdd(&g_m[tgt * H_DIM + r0],     mv.x);
    atomicAdd(&g_m[tgt * H_DIM + r0 + 1], mv.y);
    if (src != tgt) {
        atomicAdd(&g_m[src * H_DIM + r0],     mv.x);
        atomicAdd(&g_m[src * H_DIM + r0 + 1], mv.y);
    }
}

// ---------------- GRU cell: 16 nodes/block, 4 nodes/thread ----------------
#define NPB 16
__global__ __launch_bounds__(256) void k_gru(const float* __restrict__ xin,
                                             float*       __restrict__ xout,
                                             const float* __restrict__ Wih,
                                             const float* __restrict__ Whh,
                                             const float* __restrict__ bih,
                                             const float* __restrict__ bhh) {
    __shared__ float sx[NPB * H_DIM];
    __shared__ float sm[NPB * H_DIM];
    int t = threadIdx.x;
    int base = blockIdx.x * NPB * H_DIM;
    for (int i = t; i < NPB * H_DIM; i += 256) {
        sx[i] = xin[base + i];
        sm[i] = g_m[base + i];
        g_m[base + i] = 0.f;   // reset accumulator for next step / next replay
    }
    __syncthreads();

    int c  = t & 63;
    int ng = t >> 6;  // handles nodes ng*4 .. ng*4+3
    float aR[4], aZ[4], aN[4], hR[4], hZ[4], hN[4];
    float biR = bih[c], biZ = bih[64 + c], biN = bih[128 + c];
    float bhR = bhh[c], bhZ = bhh[64 + c], bhN = bhh[128 + c];
#pragma unroll
    for (int q = 0; q < 4; q++) {
        aR[q] = biR; aZ[q] = biZ; aN[q] = biN;
        hR[q] = bhR; hZ[q] = bhZ; hN[q] = bhN;
    }
#pragma unroll 4
    for (int k = 0; k < H_DIM; k++) {
        float w0 = Wih[k * 192 + c], w1 = Wih[k * 192 + 64 + c], w2 = Wih[k * 192 + 128 + c];
        float v0 = Wih[(64 + k) * 192 + c], v1 = Wih[(64 + k) * 192 + 64 + c], v2 = Wih[(64 + k) * 192 + 128 + c];
        float u0 = Whh[k * 192 + c], u1 = Whh[k * 192 + 64 + c], u2 = Whh[k * 192 + 128 + c];
#pragma unroll
        for (int q = 0; q < 4; q++) {
            float xv = sx[(ng * 4 + q) * H_DIM + k];
            float mv = sm[(ng * 4 + q) * H_DIM + k];
            aR[q] += xv * w0 + mv * v0;
            aZ[q] += xv * w1 + mv * v1;
            aN[q] += xv * w2 + mv * v2;
            hR[q] += xv * u0;
            hZ[q] += xv * u1;
            hN[q] += xv * u2;
        }
    }
#pragma unroll
    for (int q = 0; q < 4; q++) {
        float r = 1.f / (1.f + expf(-(aR[q] + hR[q])));
        float z = 1.f / (1.f + expf(-(aZ[q] + hZ[q])));
        float n = tanhf(aN[q] + r * hN[q]);
        float h = sx[(ng * 4 + q) * H_DIM + c];
        xout[base + (ng * 4 + q) * H_DIM + c] = (1.f - z) * n + z * h;
    }
}

// ---------------- launch ----------------
extern "C" void kernel_launch(void* const* d_in, const int* in_sizes, int n_in,
                              void* d_out, int out_size) {
    const float* x         = (const float*)d_in[0];
    const float* edge_data = (const float*)d_in[2];
    const int*   edges     = (const int*)  d_in[3];
    const float* W1        = (const float*)d_in[5];
    const float* b1        = (const float*)d_in[6];
    const float* W2        = (const float*)d_in[7];
    const float* b2        = (const float*)d_in[8];
    const float* W_ih      = (const float*)d_in[9];
    const float* W_hh      = (const float*)d_in[10];
    const float* b_ih      = (const float*)d_in[11];
    const float* b_hh      = (const float*)d_in[12];
    float* out = (float*)d_out;

    float *px0 = nullptr, *px1 = nullptr, *pm = nullptr;
    cudaGetSymbolAddress((void**)&px0, g_x0);
    cudaGetSymbolAddress((void**)&px1, g_x1);
    cudaGetSymbolAddress((void**)&pm,  g_m);

    cudaMemcpyAsync(px0, x, (size_t)N_NODES * H_DIM * sizeof(float),
                    cudaMemcpyDeviceToDevice, 0);
    cudaMemsetAsync(pm, 0, (size_t)N_NODES * H_DIM * sizeof(float), 0);

    k_h1<<<E_EDGES, 128>>>(edge_data, edges, W1, b1);
    k_permW2<<<(ENH_DIM * HH + 255) / 256, 256>>>(W2, b2);

    cudaFuncSetAttribute(k_gemmA, cudaFuncAttributeMaxDynamicSharedMemorySize,
                         GEMM_SMEM_BYTES);
    k_gemmA<<<dim3(H_DIM, E_EDGES / 128), 256, GEMM_SMEM_BYTES>>>();

    for (int t = 0; t < T_STEPS; t++) {
        const float* xin = (t & 1) ? px1 : px0;
        float* xout = (t == T_STEPS - 1) ? out : ((t & 1) ? px0 : px1);
        k_msg<<<(E_EDGES * 32) / 256, 256>>>(xin, edges);
        k_gru<<<N_NODES / NPB, 256>>>(xin, xout, W_ih, W_hh, b_ih, b_hh);
    }
}